// round 14
// baseline (speedup 1.0000x reference)
#include <cuda_runtime.h>

// out[n,m,:4] = relu( zw4[n] + xwb4[m] ),  zw4 = z@W1, xwb4 = x^T@W2 + b
// N=8192, M=128, DZ=DX=128, H=4.
//
// ONE kernel, 148 blocks (one wave) x 512 threads. Block owns rows
// [bid*N/148,(bid+1)*N/148) (55/56 rows); warp owns 4 consecutive rows.
// R14 change vs R13: zw uses 8-lanes-per-row -> 28 SHFL/thread (was 80),
// identical z coalescing, same FMA count. Prologue issue slots shrink.

#define N_ROWS   8192
#define M_COLS   128
#define D_Z      128
#define D_X      128
#define NBLOCKS  148
#define NTHREADS 512
#define NWARPS   (NTHREADS / 32)       // 16

__global__ __launch_bounds__(NTHREADS)
void fused_kernel(const float* __restrict__ z,
                  const float* __restrict__ x,
                  const float* __restrict__ W,
                  const float* __restrict__ b,
                  float4* __restrict__ out4)
{
    __shared__ float4 sPart[NWARPS][M_COLS];   // 32 KB xwb partials
    __shared__ float4 sXWB[M_COLS];            // 2 KB

    const int tid  = threadIdx.x;
    const int bid  = blockIdx.x;
    const int lane = tid & 31;
    const int warp = tid >> 5;                 // 0..15
    const float4* W4 = reinterpret_cast<const float4*>(W);
    const float4* x4 = reinterpret_cast<const float4*>(x);

    // Row range for this block; warp owns rows base_row .. base_row+3.
    const int r0 = (bid * N_ROWS) / NBLOCKS;
    const int r1 = ((bid + 1) * N_ROWS) / NBLOCKS;
    const int base_row = r0 + warp * 4;

    // Lane role for zw: 8 lanes per row.
    const int jrow = lane >> 3;                // 0..3 (row within warp)
    const int sub  = lane & 7;                 // 0..7 (d-octant)
    const int myrow   = base_row + jrow;
    const bool myvalid = myrow < r1;
    const int safe_row = myvalid ? myrow : (r1 - 1);

    // ---- 1) Issue z loads first: load q reads float4 index q*8+sub of my row.
    //      Per warp-LDG: each row-group reads 8 consecutive float4 = one full
    //      128B line per row -> 4 lines/instr, same coalescing as before. ----
    const float4* zr = reinterpret_cast<const float4*>(z + (size_t)safe_row * D_Z);
    float4 zq[4];
    #pragma unroll
    for (int q = 0; q < 4; ++q) zq[q] = zr[q * 8 + sub];

    // ---- 2) xwb partials while z is in flight.
    //      Warp w owns d in [8w,8w+8); lane covers m = 4*lane..4*lane+3. ----
    {
        float4 acc[4] = {{0,0,0,0},{0,0,0,0},{0,0,0,0},{0,0,0,0}};
        const int d0 = warp * 8;
        #pragma unroll
        for (int i = 0; i < 8; ++i) {
            const int d = d0 + i;
            const float4 xv = x4[d * 32 + lane];             // L2-resident
            const float4 w  = W4[D_Z + d];                   // L1 broadcast
            acc[0].x = fmaf(xv.x, w.x, acc[0].x); acc[0].y = fmaf(xv.x, w.y, acc[0].y);
            acc[0].z = fmaf(xv.x, w.z, acc[0].z); acc[0].w = fmaf(xv.x, w.w, acc[0].w);
            acc[1].x = fmaf(xv.y, w.x, acc[1].x); acc[1].y = fmaf(xv.y, w.y, acc[1].y);
            acc[1].z = fmaf(xv.y, w.z, acc[1].z); acc[1].w = fmaf(xv.y, w.w, acc[1].w);
            acc[2].x = fmaf(xv.z, w.x, acc[2].x); acc[2].y = fmaf(xv.z, w.y, acc[2].y);
            acc[2].z = fmaf(xv.z, w.z, acc[2].z); acc[2].w = fmaf(xv.z, w.w, acc[2].w);
            acc[3].x = fmaf(xv.w, w.x, acc[3].x); acc[3].y = fmaf(xv.w, w.y, acc[3].y);
            acc[3].z = fmaf(xv.w, w.z, acc[3].z); acc[3].w = fmaf(xv.w, w.w, acc[3].w);
        }
        #pragma unroll
        for (int c = 0; c < 4; ++c) sPart[warp][lane * 4 + c] = acc[c];
    }

    // ---- 3) zw: my row's partial over my 16 d (4 chunks of 4 d), then
    //      3-stage reduce over the 8-lane row-group + gather broadcast. ----
    float4 a[4];
    {
        float4 t = make_float4(0.f, 0.f, 0.f, 0.f);
        #pragma unroll
        for (int q = 0; q < 4; ++q) {
            const int db = q * 32 + sub * 4;       // this chunk's first d
            const float4 w0 = W4[db + 0];          // L1-hot (2 KB)
            const float4 w1 = W4[db + 1];
            const float4 w2 = W4[db + 2];
            const float4 w3 = W4[db + 3];
            t.x = fmaf(zq[q].x, w0.x, t.x); t.y = fmaf(zq[q].x, w0.y, t.y);
            t.z = fmaf(zq[q].x, w0.z, t.z); t.w = fmaf(zq[q].x, w0.w, t.w);
            t.x = fmaf(zq[q].y, w1.x, t.x); t.y = fmaf(zq[q].y, w1.y, t.y);
            t.z = fmaf(zq[q].y, w1.z, t.z); t.w = fmaf(zq[q].y, w1.w, t.w);
            t.x = fmaf(zq[q].z, w2.x, t.x); t.y = fmaf(zq[q].z, w2.y, t.y);
            t.z = fmaf(zq[q].z, w2.z, t.z); t.w = fmaf(zq[q].z, w2.w, t.w);
            t.x = fmaf(zq[q].w, w3.x, t.x); t.y = fmaf(zq[q].w, w3.y, t.y);
            t.z = fmaf(zq[q].w, w3.z, t.z); t.w = fmaf(zq[q].w, w3.w, t.w);
        }
        #pragma unroll
        for (int off = 1; off <= 4; off <<= 1) {   // reduce within 8-lane group
            t.x += __shfl_xor_sync(0xffffffffu, t.x, off);
            t.y += __shfl_xor_sync(0xffffffffu, t.y, off);
            t.z += __shfl_xor_sync(0xffffffffu, t.z, off);
            t.w += __shfl_xor_sync(0xffffffffu, t.w, off);
        }
        // Gather: row j's sum lives in lanes [8j,8j+8); broadcast all 4 rows.
        #pragma unroll
        for (int j = 0; j < 4; ++j) {
            a[j].x = __shfl_sync(0xffffffffu, t.x, j * 8);
            a[j].y = __shfl_sync(0xffffffffu, t.y, j * 8);
            a[j].z = __shfl_sync(0xffffffffu, t.z, j * 8);
            a[j].w = __shfl_sync(0xffffffffu, t.w, j * 8);
        }
    }
    __syncthreads();

    // ---- 4) Fold xwb partials: 128 threads, 16-way add + bias ----
    if (tid < M_COLS) {
        float4 s = *reinterpret_cast<const float4*>(b);
        #pragma unroll
        for (int w = 0; w < NWARPS; ++w) {
            const float4 p = sPart[w][tid];
            s.x += p.x; s.y += p.y; s.z += p.z; s.w += p.w;
        }
        sXWB[tid] = s;
    }
    __syncthreads();

    // ---- 5) Stream straight from registers: up to 16 STG.128/thread ----
    const float4 c0 = sXWB[lane];
    const float4 c1 = sXWB[lane + 32];
    const float4 c2 = sXWB[lane + 64];
    const float4 c3 = sXWB[lane + 96];

    #pragma unroll
    for (int j = 0; j < 4; ++j) {
        const int row = base_row + j;
        if (row < r1) {
            float4* __restrict__ o = out4 + ((size_t)row << 7);  // row*128
            float4 r;
            r.x = fmaxf(a[j].x + c0.x, 0.f); r.y = fmaxf(a[j].y + c0.y, 0.f);
            r.z = fmaxf(a[j].z + c0.z, 0.f); r.w = fmaxf(a[j].w + c0.w, 0.f);
            o[lane] = r;
            r.x = fmaxf(a[j].x + c1.x, 0.f); r.y = fmaxf(a[j].y + c1.y, 0.f);
            r.z = fmaxf(a[j].z + c1.z, 0.f); r.w = fmaxf(a[j].w + c1.w, 0.f);
            o[lane + 32] = r;
            r.x = fmaxf(a[j].x + c2.x, 0.f); r.y = fmaxf(a[j].y + c2.y, 0.f);
            r.z = fmaxf(a[j].z + c2.z, 0.f); r.w = fmaxf(a[j].w + c2.w, 0.f);
            o[lane + 64] = r;
            r.x = fmaxf(a[j].x + c3.x, 0.f); r.y = fmaxf(a[j].y + c3.y, 0.f);
            r.z = fmaxf(a[j].z + c3.z, 0.f); r.w = fmaxf(a[j].w + c3.w, 0.f);
            o[lane + 96] = r;
        }
    }
}

extern "C" void kernel_launch(void* const* d_in, const int* in_sizes, int n_in,
                              void* d_out, int out_size)
{
    const float* z = (const float*)d_in[0];   // [8192,128]
    const float* x = (const float*)d_in[1];   // [128,128]
    const float* W = (const float*)d_in[2];   // [256,4]
    const float* b = (const float*)d_in[3];   // [4]
    float4* out4   = (float4*)d_out;

    fused_kernel<<<NBLOCKS, NTHREADS>>>(z, x, W, b, out4);
}